// round 1
// baseline (speedup 1.0000x reference)
#include <cuda_runtime.h>
#include <math.h>

#define BSZ 4
#define CH  128
#define HH  128
#define WW  128
#define HWP (HH*WW)

// -------- scratch (static device memory; no allocations) --------
__device__ float g_r1 [(size_t)BSZ*CH*HWP];   // bn1 output
__device__ float g_d1 [(size_t)BSZ*CH*HWP];   // layer1 output (post-prelu)
__device__ float g_offm[(size_t)BSZ*27*HWP];  // ch 0..17 offsets, 18..26 mask
__device__ float g_wT1[9*CH*CH];              // w1 transposed [k][c][co]
__device__ float g_wT2[9*CH*CH];              // w2 transposed [k][c][co]

// -------- prep: transpose main conv weights to [k][c][co] --------
__global__ void prep_wt_kernel(const float* __restrict__ w1, const float* __restrict__ w2){
    int i = blockIdx.x*256 + threadIdx.x;
    const int N = 9*CH*CH;
    if (i >= 2*N) return;
    const float* w = (i < N) ? w1 : w2;
    float*       o = (i < N) ? g_wT1 : g_wT2;
    int j = (i < N) ? i : i - N;
    int co = j & (CH-1);
    int c  = (j >> 7) & (CH-1);
    int k  = j >> 14;
    o[j] = w[(co*CH + c)*9 + k];
}

// -------- bn1 elementwise --------
__global__ void bn1_kernel(const float4* __restrict__ x,
                           const float* __restrict__ g, const float* __restrict__ b,
                           const float* __restrict__ m, const float* __restrict__ v){
    int i = blockIdx.x*256 + threadIdx.x;          // over BSZ*CH*HWP/4 float4s
    int c = (i >> 12) & (CH-1);                    // (i*4 / HWP) % CH
    float s  = g[c] * rsqrtf(v[c] + 1e-5f);
    float bb = b[c] - m[c]*s;
    float4 xv = x[i];
    float4 r;
    r.x = xv.x*s + bb; r.y = xv.y*s + bb; r.z = xv.z*s + bb; r.w = xv.w*s + bb;
    ((float4*)g_r1)[i] = r;
}

// -------- fused offset(18) + mask(9) 3x3 conv, pad 1 --------
// grid: 128 blocks = BSZ * (HH/4).  block: 256 thr, 2 px/thread (4 rows x 128 cols tile)
__global__ void offmod_kernel(const float* __restrict__ src,
                              const float* __restrict__ offw, const float* __restrict__ offb,
                              const float* __restrict__ modw, const float* __restrict__ modb){
    extern __shared__ float sm[];
    float* wsm   = sm;              // [c*9+k][27]  -> 1152*27 floats
    float* patch = sm + 1152*27;    // 6 x 130 floats

    int t  = threadIdx.x;
    int b  = blockIdx.x >> 5;
    int h0 = (blockIdx.x & 31) * 4;

    // stage all 27x128x9 weights into smem (contiguous global reads)
    for (int i = t; i < 27*1152; i += 256){
        int co = i / 1152;
        int r  = i - co*1152;       // r = c*9 + k
        float val = (co < 18) ? offw[co*1152 + r] : modw[(co-18)*1152 + r];
        wsm[r*27 + co] = val;
    }

    int p0 = 2*t;
    int tr = p0 >> 7;               // tile row 0..3
    int tw = p0 & 127;              // even col

    float acc0[27], acc1[27];
#pragma unroll
    for (int j = 0; j < 27; j++){ acc0[j] = 0.f; acc1[j] = 0.f; }

    for (int c = 0; c < CH; c++){
        __syncthreads();
        const float* sp = src + ((size_t)(b*CH + c))*HWP;
        for (int i = t; i < 780; i += 256){
            int pr = i / 130; int pc = i - pr*130;
            int y  = h0 - 1 + pr;
            int xx = pc - 1;
            float vv = 0.f;
            if ((unsigned)y < HH && (unsigned)xx < WW) vv = sp[y*WW + xx];
            patch[i] = vv;
        }
        __syncthreads();
        const float* wrow = wsm + c*9*27;
#pragma unroll
        for (int k = 0; k < 9; k++){
            int ky = k/3, kx = k - ky*3;
            float v0 = patch[(tr+ky)*130 + tw + kx];
            float v1 = patch[(tr+ky)*130 + tw + kx + 1];
            const float* wk = wrow + k*27;
#pragma unroll
            for (int co = 0; co < 27; co++){
                float wv = wk[co];
                acc0[co] += wv*v0;
                acc1[co] += wv*v1;
            }
        }
    }

    int h = h0 + tr;
    size_t pbase = (size_t)h*WW + tw;
#pragma unroll
    for (int co = 0; co < 27; co++){
        float a0, a1;
        if (co < 18){
            float bb = offb[co];
            a0 = acc0[co] + bb; a1 = acc1[co] + bb;
        } else {
            float bb = modb[co-18];
            a0 = 2.f/(1.f + __expf(-(acc0[co] + bb)));
            a1 = 2.f/(1.f + __expf(-(acc1[co] + bb)));
        }
        float* op = g_offm + ((size_t)(b*27 + co))*HWP + pbase;
        *(float2*)op = make_float2(a0, a1);
    }
}

// -------- deformable conv implicit GEMM --------
// grid: 1024 blocks = BSZ*HH*2 ; block 256 thr; tile = 64 px (one h-row half)
// MODE 0: out = prelu(conv) -> g_d1  (p0 = alpha)
// MODE 1: out = bn2(conv) + x -> d_out (p0 = x, bn params used)
template<int MODE>
__global__ void __launch_bounds__(256)
deform_kernel(const float* __restrict__ src, const float* __restrict__ wT,
              const float* __restrict__ p0,
              const float* __restrict__ bn_g, const float* __restrict__ bn_b,
              const float* __restrict__ bn_m, const float* __restrict__ bn_v,
              float* __restrict__ out){
    __shared__ float cols[CH*64];     // [c][px]
    __shared__ float s_wt[64*4];
    __shared__ int   s_ad[64*4];

    int t   = threadIdx.x;
    int b   = blockIdx.x >> 8;
    int rem = blockIdx.x & 255;
    int h   = rem >> 1;
    int w0  = (rem & 1) << 6;

    int tx  = t & 15;
    int ty  = t >> 4;
    int ty2 = ty*2;
    int pxme = t & 63;

    float acc[8][4];
#pragma unroll
    for (int j = 0; j < 8; j++)
#pragma unroll
        for (int i = 0; i < 4; i++) acc[j][i] = 0.f;

    const float* srcb  = src + (size_t)b*CH*HWP;
    const float* offb_ = g_offm + (size_t)b*27*HWP;

    for (int k = 0; k < 9; k++){
        __syncthreads();
        if (t < 64){
            int w = w0 + t;
            int p = h*WW + w;
            float oy = offb_[(2*k  )*HWP + p];
            float ox = offb_[(2*k+1)*HWP + p];
            float mv = offb_[(18+k )*HWP + p];
            int ky = k/3, kx = k - ky*3;
            float py  = (float)(h - 1 + ky) + oy;
            float pxf = (float)(w - 1 + kx) + ox;
            float y0f = floorf(py), x0f = floorf(pxf);
            float ay = py - y0f, ax = pxf - x0f;
            int y0 = (int)y0f, x0 = (int)x0f;
#pragma unroll
            for (int j = 0; j < 4; j++){
                int dy = j >> 1, dx = j & 1;
                int yi = y0 + dy, xi = x0 + dx;
                bool ok = ((unsigned)yi < HH) && ((unsigned)xi < WW);
                int yc = min(max(yi, 0), HH-1);
                int xc = min(max(xi, 0), WW-1);
                float wy = dy ? ay : 1.f - ay;
                float wx = dx ? ax : 1.f - ax;
                s_ad[t*4+j] = yc*WW + xc;
                s_wt[t*4+j] = ok ? wy*wx*mv : 0.f;
            }
        }
        __syncthreads();

        // sample cols[c][px] for this k
        int a0 = s_ad[pxme*4+0], a1 = s_ad[pxme*4+1], a2 = s_ad[pxme*4+2], a3 = s_ad[pxme*4+3];
        float f0 = s_wt[pxme*4+0], f1 = s_wt[pxme*4+1], f2 = s_wt[pxme*4+2], f3 = s_wt[pxme*4+3];
        int cstart = t >> 6;
#pragma unroll 8
        for (int s = 0; s < 32; s++){
            int c = cstart + s*4;
            const float* sp = srcb + (size_t)c*HWP;
            float v = f0*sp[a0] + f1*sp[a1] + f2*sp[a2] + f3*sp[a3];
            cols[c*64 + pxme] = v;
        }
        __syncthreads();

        // GEMM fragment: acc[co 8][px 4] += w_k[c][co] * cols[c][px]
        const float4* c4 = (const float4*)cols;
        const float4* w4 = (const float4*)(wT + (size_t)k*CH*CH);
#pragma unroll 4
        for (int c = 0; c < CH; c++){
            float4 cv = c4[c*16 + tx];
            float4 wa = w4[c*32 + ty2];
            float4 wb = w4[c*32 + ty2 + 1];
            float wv;
            wv = wa.x; acc[0][0]+=wv*cv.x; acc[0][1]+=wv*cv.y; acc[0][2]+=wv*cv.z; acc[0][3]+=wv*cv.w;
            wv = wa.y; acc[1][0]+=wv*cv.x; acc[1][1]+=wv*cv.y; acc[1][2]+=wv*cv.z; acc[1][3]+=wv*cv.w;
            wv = wa.z; acc[2][0]+=wv*cv.x; acc[2][1]+=wv*cv.y; acc[2][2]+=wv*cv.z; acc[2][3]+=wv*cv.w;
            wv = wa.w; acc[3][0]+=wv*cv.x; acc[3][1]+=wv*cv.y; acc[3][2]+=wv*cv.z; acc[3][3]+=wv*cv.w;
            wv = wb.x; acc[4][0]+=wv*cv.x; acc[4][1]+=wv*cv.y; acc[4][2]+=wv*cv.z; acc[4][3]+=wv*cv.w;
            wv = wb.y; acc[5][0]+=wv*cv.x; acc[5][1]+=wv*cv.y; acc[5][2]+=wv*cv.z; acc[5][3]+=wv*cv.w;
            wv = wb.z; acc[6][0]+=wv*cv.x; acc[6][1]+=wv*cv.y; acc[6][2]+=wv*cv.z; acc[6][3]+=wv*cv.w;
            wv = wb.w; acc[7][0]+=wv*cv.x; acc[7][1]+=wv*cv.y; acc[7][2]+=wv*cv.z; acc[7][3]+=wv*cv.w;
        }
    }

    // epilogue
    int co0  = ty*8;
    int wcol = w0 + tx*4;
    size_t obase = ((size_t)b*CH)*HWP + (size_t)h*WW + wcol;
    if (MODE == 0){
#pragma unroll
        for (int j = 0; j < 8; j++){
            int co = co0 + j;
            float a = p0[co];            // alpha
            float4 o;
            o.x = acc[j][0] > 0.f ? acc[j][0] : a*acc[j][0];
            o.y = acc[j][1] > 0.f ? acc[j][1] : a*acc[j][1];
            o.z = acc[j][2] > 0.f ? acc[j][2] : a*acc[j][2];
            o.w = acc[j][3] > 0.f ? acc[j][3] : a*acc[j][3];
            *(float4*)(out + obase + (size_t)co*HWP) = o;
        }
    } else {
#pragma unroll
        for (int j = 0; j < 8; j++){
            int co = co0 + j;
            float s  = bn_g[co] * rsqrtf(bn_v[co] + 1e-5f);
            float bb = bn_b[co] - bn_m[co]*s;
            float4 xv = *(const float4*)(p0 + obase + (size_t)co*HWP);  // shortcut x
            float4 o;
            o.x = acc[j][0]*s + bb + xv.x;
            o.y = acc[j][1]*s + bb + xv.y;
            o.z = acc[j][2]*s + bb + xv.z;
            o.w = acc[j][3]*s + bb + xv.w;
            *(float4*)(out + obase + (size_t)co*HWP) = o;
        }
    }
}

// -------- host launcher --------
extern "C" void kernel_launch(void* const* d_in, const int* in_sizes, int n_in,
                              void* d_out, int out_size){
    const float* x      = (const float*)d_in[0];
    const float* bn1_g  = (const float*)d_in[1];
    const float* bn1_b  = (const float*)d_in[2];
    const float* bn1_m  = (const float*)d_in[3];
    const float* bn1_v  = (const float*)d_in[4];
    const float* off1_w = (const float*)d_in[5];
    const float* off1_b = (const float*)d_in[6];
    const float* mod1_w = (const float*)d_in[7];
    const float* mod1_b = (const float*)d_in[8];
    const float* w1     = (const float*)d_in[9];
    const float* alpha  = (const float*)d_in[10];
    const float* off2_w = (const float*)d_in[11];
    const float* off2_b = (const float*)d_in[12];
    const float* mod2_w = (const float*)d_in[13];
    const float* mod2_b = (const float*)d_in[14];
    const float* w2     = (const float*)d_in[15];
    const float* bn2_g  = (const float*)d_in[16];
    const float* bn2_b  = (const float*)d_in[17];
    const float* bn2_m  = (const float*)d_in[18];
    const float* bn2_v  = (const float*)d_in[19];
    float* out = (float*)d_out;

    float *r1p, *d1p, *wt1p, *wt2p;
    cudaGetSymbolAddress((void**)&r1p,  g_r1);
    cudaGetSymbolAddress((void**)&d1p,  g_d1);
    cudaGetSymbolAddress((void**)&wt1p, g_wT1);
    cudaGetSymbolAddress((void**)&wt2p, g_wT2);

    const int OFFMOD_SMEM = (1152*27 + 780) * (int)sizeof(float);   // ~127.5 KB
    cudaFuncSetAttribute(offmod_kernel, cudaFuncAttributeMaxDynamicSharedMemorySize, OFFMOD_SMEM);

    // 1) weight transposes
    prep_wt_kernel<<<(2*9*CH*CH + 255)/256, 256>>>(w1, w2);
    // 2) bn1
    bn1_kernel<<<(BSZ*CH*HWP/4)/256, 256>>>((const float4*)x, bn1_g, bn1_b, bn1_m, bn1_v);
    // 3) offsets + mask for layer 1
    offmod_kernel<<<128, 256, OFFMOD_SMEM>>>(r1p, off1_w, off1_b, mod1_w, mod1_b);
    // 4) deform conv 1 (+prelu) -> d1
    deform_kernel<0><<<1024, 256>>>(r1p, wt1p, alpha, nullptr, nullptr, nullptr, nullptr, d1p);
    // 5) offsets + mask for layer 2
    offmod_kernel<<<128, 256, OFFMOD_SMEM>>>(d1p, off2_w, off2_b, mod2_w, mod2_b);
    // 6) deform conv 2 (+bn2 +shortcut) -> out
    deform_kernel<1><<<1024, 256>>>(d1p, wt2p, x, bn2_g, bn2_b, bn2_m, bn2_v, out);
}